// round 9
// baseline (speedup 1.0000x reference)
#include <cuda_runtime.h>
#include <cstdint>

#define B_   512
#define M_   256
#define BM_  (B_*M_)      // 131072 rows
#define NGL  4

// Scratch (allocation-free rule: __device__ globals)
__device__ float g_X[BM_*128];

// ---------------------------------------------------------------------------
// helpers
// ---------------------------------------------------------------------------
__device__ __forceinline__ uint32_t f2tf(float x) {
    uint32_t r;
    asm("cvt.rna.tf32.f32 %0, %1;" : "=r"(r) : "f"(x));
    return r;
}

__device__ __forceinline__ void mma8(float& c0, float& c1, float& c2, float& c3,
                                     uint32_t a0, uint32_t a1, uint32_t a2, uint32_t a3,
                                     uint32_t b0, uint32_t b1)
{
    asm volatile(
        "mma.sync.aligned.m16n8k8.row.col.f32.tf32.tf32.f32 "
        "{%0,%1,%2,%3}, {%4,%5,%6,%7}, {%8,%9}, {%0,%1,%2,%3};"
        : "+f"(c0), "+f"(c1), "+f"(c2), "+f"(c3)
        : "r"(a0), "r"(a1), "r"(a2), "r"(a3), "r"(b0), "r"(b1));
}

__device__ __forceinline__ uint32_t sptr(const void* p) {
    return (uint32_t)__cvta_generic_to_shared(p);
}
__device__ __forceinline__ void cp16(uint32_t s, const void* g) {
    asm volatile("cp.async.cg.shared.global [%0], [%1], 16;" :: "r"(s), "l"(g));
}
__device__ __forceinline__ void cp_commit() {
    asm volatile("cp.async.commit_group;");
}
template<int N> __device__ __forceinline__ void cp_wait() {
    asm volatile("cp.async.wait_group %0;" :: "n"(N));
}

// ===========================================================================
// Fully-fused 4-layer GNN: one block per batch (grid 512, 512 threads).
// smem: Y tile 256x128 swizzled (128 KB) + 2 A-chunk slots (256x32, 32 KB ea)
//       + 2 W-chunk slots (128x32, 16 KB ea) = 224 KB.
// Per layer:  phase1  Y(smem) = x @ Wl^T + bl      (x from global, K=128)
//             phase2  x'(global, in place) = relu(G0[b] @ Y)   (K=256)
// Swizzles (conflict-free fragment reads):
//   chunk tiles [r][32]:  phys col = k ^ ((r&7)<<2)
//   Y tile [k][128]:      phys col = p ^ ((k&3)<<3)
// ===========================================================================
#define YT_F    (256*128)      // 32768 floats
#define ACHK_F  (256*32)       // 8192
#define WCHK_F  (128*32)       // 4096
#define DSMEM_GNN ((YT_F + 2*ACHK_F + 2*WCHK_F)*4)   // 229376 B

__global__ __launch_bounds__(512, 1)
void gnn_fused(const float* __restrict__ G, const float* __restrict__ xG,
               const float* __restrict__ gmlW, const float* __restrict__ gmlB,
               float* __restrict__ X)
{
    extern __shared__ float sm[];
    float* Ys = sm;                          // [256][128] swizzled
    float* Asl[2] = { sm + YT_F, sm + YT_F + ACHK_F };
    float* Wsl[2] = { sm + YT_F + 2*ACHK_F, sm + YT_F + 2*ACHK_F + WCHK_F };

    const int tid  = threadIdx.x;
    const int lane = tid & 31, wid = tid >> 5;       // wid 0..15
    const int g = lane >> 2, t = lane & 3;
    const int m0 = (wid >> 2) * 64;                  // 0,64,128,192
    const int n0 = (wid & 3) * 32;
    const int b = blockIdx.x;

    const float* Gb = G + (long)b * M_ * M_;
    const float* x0 = xG + (long)b * M_ * 128;
    float*       xo = X  + (long)b * M_ * 128;

    const int swA = g << 2;        // chunk swizzle term for frag reads
    const int swY = t << 3;        // Y swizzle term for b-frag reads
    const int swW = (g & 3) << 3;  // Y swizzle term for epilogue writes

    float acc[4][4][4];

    for (int l = 0; l < NGL; l++) {
        const float* xin  = (l == 0) ? x0 : xo;
        const float* Wl   = gmlW + (long)l * 16384;
        const float* bl   = gmlB + l * 128;

        // ---------------- phase 1: Y = xin @ Wl^T + bl ----------------
        auto fill1 = [&](int s, int kc) {
            float* A_s = Asl[s];
            float* W_s = Wsl[s];
#pragma unroll
            for (int it = 0; it < 4; it++) {         // x chunk: 256x32
                int v = tid + it * 512;
                int rr = v >> 3, cc = (v & 7) * 4;
                cp16(sptr(&A_s[rr * 32 + (cc ^ ((rr & 7) << 2))]),
                     &xin[rr * 128 + kc + cc]);
            }
#pragma unroll
            for (int it = 0; it < 2; it++) {         // W chunk: 128x32
                int v = tid + it * 512;
                int rr = v >> 3, cc = (v & 7) * 4;
                cp16(sptr(&W_s[rr * 32 + (cc ^ ((rr & 7) << 2))]),
                     &Wl[rr * 128 + kc + cc]);
            }
        };

#pragma unroll
        for (int i = 0; i < 4; i++)
#pragma unroll
            for (int j = 0; j < 4; j++)
#pragma unroll
                for (int z = 0; z < 4; z++) acc[i][j][z] = 0.f;

        fill1(0, 0); cp_commit();
#pragma unroll
        for (int c = 0; c < 4; c++) {
            if (c + 1 < 4) { fill1((c + 1) & 1, (c + 1) * 32); cp_commit(); cp_wait<1>(); }
            else           { cp_wait<0>(); }
            __syncthreads();
            const float* A_s = Asl[c & 1];
            const float* W_s = Wsl[c & 1];
#pragma unroll
            for (int ks = 0; ks < 4; ks++) {
                const int k0 = ks * 8;
                uint32_t af[4][4];
#pragma unroll
                for (int i = 0; i < 4; i++) {
                    int r0 = m0 + 16 * i + g;        // (r&7)==g
                    af[i][0] = f2tf(A_s[ r0      * 32 + ((k0 + t    ) ^ swA)]);
                    af[i][1] = f2tf(A_s[(r0 + 8) * 32 + ((k0 + t    ) ^ swA)]);
                    af[i][2] = f2tf(A_s[ r0      * 32 + ((k0 + t + 4) ^ swA)]);
                    af[i][3] = f2tf(A_s[(r0 + 8) * 32 + ((k0 + t + 4) ^ swA)]);
                }
                uint32_t bf[4][2];
#pragma unroll
                for (int j = 0; j < 4; j++) {
                    int nb = n0 + 8 * j + g;         // (nb&7)==g
                    bf[j][0] = f2tf(W_s[nb * 32 + ((k0 + t    ) ^ swA)]);
                    bf[j][1] = f2tf(W_s[nb * 32 + ((k0 + t + 4) ^ swA)]);
                }
#pragma unroll
                for (int i = 0; i < 4; i++)
#pragma unroll
                    for (int j = 0; j < 4; j++)
                        mma8(acc[i][j][0], acc[i][j][1], acc[i][j][2], acc[i][j][3],
                             af[i][0], af[i][1], af[i][2], af[i][3],
                             bf[j][0], bf[j][1]);
            }
            __syncthreads();
        }

        // prefetch first G chunk while writing Y epilogue
        auto fillG = [&](int s, int kc) {
            float* A_s = Asl[s];
#pragma unroll
            for (int it = 0; it < 4; it++) {         // G chunk: 256x32
                int v = tid + it * 512;
                int rr = v >> 3, cc = (v & 7) * 4;
                cp16(sptr(&A_s[rr * 32 + (cc ^ ((rr & 7) << 2))]),
                     &Gb[rr * 256 + kc + cc]);
            }
        };
        fillG(0, 0); cp_commit();

        // epilogue: Y(smem, swizzled) = acc + bias
#pragma unroll
        for (int j = 0; j < 4; j++) {
            int col = n0 + 8 * j + 2 * t;
            float bv0 = bl[col], bv1 = bl[col + 1];
#pragma unroll
            for (int i = 0; i < 4; i++) {
                int r0 = m0 + 16 * i + g;            // (r&3)==(g&3)
                int r1 = r0 + 8;
                *(float2*)&Ys[r0 * 128 + (col ^ swW)] =
                    make_float2(acc[i][j][0] + bv0, acc[i][j][1] + bv1);
                *(float2*)&Ys[r1 * 128 + (col ^ swW)] =
                    make_float2(acc[i][j][2] + bv0, acc[i][j][3] + bv1);
            }
        }

        // ---------------- phase 2: x' = relu(Gb @ Y) ----------------
#pragma unroll
        for (int i = 0; i < 4; i++)
#pragma unroll
            for (int j = 0; j < 4; j++)
#pragma unroll
                for (int z = 0; z < 4; z++) acc[i][j][z] = 0.f;

        for (int c = 0; c < 8; c++) {
            if (c + 1 < 8) { fillG((c + 1) & 1, (c + 1) * 32); cp_commit(); cp_wait<1>(); }
            else           { cp_wait<0>(); }
            __syncthreads();                          // also publishes Y (c==0)
            const float* A_s = Asl[c & 1];
            const int kc = c * 32;
#pragma unroll
            for (int ks = 0; ks < 4; ks++) {
                const int k0 = ks * 8;
                uint32_t af[4][4];
#pragma unroll
                for (int i = 0; i < 4; i++) {
                    int r0 = m0 + 16 * i + g;
                    af[i][0] = f2tf(A_s[ r0      * 32 + ((k0 + t    ) ^ swA)]);
                    af[i][1] = f2tf(A_s[(r0 + 8) * 32 + ((k0 + t    ) ^ swA)]);
                    af[i][2] = f2tf(A_s[ r0      * 32 + ((k0 + t + 4) ^ swA)]);
                    af[i][3] = f2tf(A_s[(r0 + 8) * 32 + ((k0 + t + 4) ^ swA)]);
                }
                uint32_t bf[4][2];
                const int kr0 = (kc + k0 + t) * 128;      // (k&3)==t
                const int kr1 = (kc + k0 + t + 4) * 128;  // (k&3)==t
#pragma unroll
                for (int j = 0; j < 4; j++) {
                    int p = n0 + 8 * j + g;
                    bf[j][0] = f2tf(Ys[kr0 + (p ^ swY)]);
                    bf[j][1] = f2tf(Ys[kr1 + (p ^ swY)]);
                }
#pragma unroll
                for (int i = 0; i < 4; i++)
#pragma unroll
                    for (int j = 0; j < 4; j++)
                        mma8(acc[i][j][0], acc[i][j][1], acc[i][j][2], acc[i][j][3],
                             af[i][0], af[i][1], af[i][2], af[i][3],
                             bf[j][0], bf[j][1]);
            }
            __syncthreads();
        }

        // epilogue: xo(global, in place) = relu(acc)
#pragma unroll
        for (int j = 0; j < 4; j++) {
            int col = n0 + 8 * j + 2 * t;
#pragma unroll
            for (int i = 0; i < 4; i++) {
                int r0 = m0 + 16 * i + g;
                int r1 = r0 + 8;
                *(float2*)&xo[r0 * 128 + col] =
                    make_float2(fmaxf(acc[i][j][0], 0.f), fmaxf(acc[i][j][1], 0.f));
                *(float2*)&xo[r1 * 128 + col] =
                    make_float2(fmaxf(acc[i][j][2], 0.f), fmaxf(acc[i][j][3], 0.f));
            }
        }
        __syncthreads();   // publish xo to the block before next layer's cp.async
    }
}

// ===========================================================================
// Mega-fused trunk + head (unchanged from R8 — passing).
// ===========================================================================
#define ASTR 36
#define TILE_F   (128*ASTR)
#define HTILE_F  (128*128)
#define WCHK_TF  TILE_F
#define DSMEM_TRUNK ((2*HTILE_F + 2*WCHK_TF)*4)   // 167936 B
#define NSTG 17
#define NSLOT (NSTG*4)

__device__ __forceinline__ void compute_chunk_swz(const float* __restrict__ H_s,
                                                  const float* __restrict__ W_s,
                                                  int kc, int m0, int n0,
                                                  int g, int t,
                                                  float acc[4][4][4])
{
    const int sw = g << 2;
#pragma unroll
    for (int ks = 0; ks < 4; ks++) {
        const int k0 = ks * 8;
        uint32_t af[4][4];
#pragma unroll
        for (int i = 0; i < 4; i++) {
            int r0 = m0 + 16 * i + g;
            int r1 = r0 + 8;
            af[i][0] = f2tf(H_s[r0 * 128 + ((kc + k0 + t    ) ^ sw)]);
            af[i][1] = f2tf(H_s[r1 * 128 + ((kc + k0 + t    ) ^ sw)]);
            af[i][2] = f2tf(H_s[r0 * 128 + ((kc + k0 + t + 4) ^ sw)]);
            af[i][3] = f2tf(H_s[r1 * 128 + ((kc + k0 + t + 4) ^ sw)]);
        }
        uint32_t bf[4][2];
#pragma unroll
        for (int j = 0; j < 4; j++) {
            int nb = n0 + 8 * j + g;
            bf[j][0] = f2tf(W_s[nb * ASTR + k0 + t]);
            bf[j][1] = f2tf(W_s[nb * ASTR + k0 + t + 4]);
        }
#pragma unroll
        for (int i = 0; i < 4; i++)
#pragma unroll
            for (int j = 0; j < 4; j++)
                mma8(acc[i][j][0], acc[i][j][1], acc[i][j][2], acc[i][j][3],
                     af[i][0], af[i][1], af[i][2], af[i][3],
                     bf[j][0], bf[j][1]);
    }
}

__global__ __launch_bounds__(256, 1)
void trunk_head_fused(const float* __restrict__ X,
    const float* __restrict__ lin0W, const float* __restrict__ lin0B,
    const float* __restrict__ rinW,  const float* __restrict__ rinB,
    const float* __restrict__ rb1W,  const float* __restrict__ rb1B,
    const float* __restrict__ rb2W,
    const float* __restrict__ routW, const float* __restrict__ routB,
    const float* __restrict__ f1W,   const float* __restrict__ f1B,
    const float* __restrict__ f2W,   const float* __restrict__ f2B,
    float* __restrict__ out)
{
    extern __shared__ float sm[];
    float* H0 = sm;
    float* H1 = sm + HTILE_F;
    float* Wc = sm + 2 * HTILE_F;

    const int tid  = threadIdx.x;
    const int lane = tid & 31, wid = tid >> 5;
    const int g = lane >> 2, t = lane & 3;
    const int m0 = (wid >> 2) * 64;
    const int n0 = (wid & 3) * 32;
    const long row0 = (long)blockIdx.x * 128;

    const float* wp[NSTG];
    wp[0] = lin0W;  wp[1] = rinW;
    wp[2] = rb1W;            wp[3] = rb2W;
    wp[4] = rb1W + 16384;    wp[5] = rb2W + 16384;
    wp[6] = rb1W + 32768;    wp[7] = rb2W + 32768;
    wp[8] = routW;
#pragma unroll
    for (int i = 0; i < 8; i++) wp[9 + i] = f1W + (long)i * 16384;
    const float* bp[9] = { lin0B, rinB, rb1B, nullptr, rb1B + 128, nullptr,
                           rb1B + 256, nullptr, routB };

    auto fillWchunk = [&](int buf, int slot) {
        const float* Wp = wp[slot >> 2];
        int kc = (slot & 3) * 32;
        float* W_s = Wc + buf * WCHK_TF;
#pragma unroll
        for (int it = 0; it < 4; it++) {
            int v = tid + it * 256;
            int rr = v >> 3, cc = (v & 7) * 4;
            cp16(sptr(&W_s[rr * ASTR + cc]), &Wp[rr * 128 + kc + cc]);
        }
    };

#pragma unroll
    for (int it = 0; it < 16; it++) {
        int v = tid + it * 256;
        int rr = v >> 5, cc = (v & 31) * 4;
        cp16(sptr(&H0[rr * 128 + (cc ^ ((rr & 7) << 2))]),
             &X[(row0 + rr) * 128 + cc]);
    }
    fillWchunk(0, 0);
    cp_commit(); cp_wait<0>(); __syncthreads();

    float psum[8];
#pragma unroll
    for (int q = 0; q < 8; q++) psum[q] = 0.f;

    float acc[4][4][4];

    for (int q = 0; q < NSLOT; q++) {
        const int s = q >> 2, c = q & 3;

        if (q + 1 < NSLOT) { fillWchunk((q + 1) & 1, q + 1); cp_commit(); }

        if (c == 0) {
#pragma unroll
            for (int i = 0; i < 4; i++)
#pragma unroll
                for (int j = 0; j < 4; j++)
#pragma unroll
                    for (int z = 0; z < 4; z++) acc[i][j][z] = 0.f;
        }

        const float* A_s = ((s & 1) || s >= 9) ? H1 : H0;
        compute_chunk_swz(A_s, Wc + (q & 1) * WCHK_TF, c * 32, m0, n0, g, t, acc);

        if (c == 3) {
            if (s < 9) {
                float* D = (s & 1) ? H0 : H1;
                const bool relu = (s == 2 || s == 4 || s == 6);
                const bool res  = (s == 3 || s == 5 || s == 7);
                const float* bias = bp[s];
                const int sw = g << 2;
#pragma unroll
                for (int j = 0; j < 4; j++) {
                    int col = n0 + 8 * j + 2 * t;
                    float bv0 = bias ? bias[col]     : 0.f;
                    float bv1 = bias ? bias[col + 1] : 0.f;
#pragma unroll
                    for (int i = 0; i < 4; i++) {
                        int r0 = m0 + 16 * i + g;
                        int r1 = r0 + 8;
                        int p0 = r0 * 128 + (col ^ sw);
                        int p1 = r1 * 128 + (col ^ sw);
                        float v00 = acc[i][j][0] + bv0, v01 = acc[i][j][1] + bv1;
                        float v10 = acc[i][j][2] + bv0, v11 = acc[i][j][3] + bv1;
                        if (relu) { v00 = fmaxf(v00, 0.f); v01 = fmaxf(v01, 0.f);
                                    v10 = fmaxf(v10, 0.f); v11 = fmaxf(v11, 0.f); }
                        if (res) {
                            float2 e0 = *(const float2*)&D[p0];
                            float2 e1 = *(const float2*)&D[p1];
                            v00 += e0.x; v01 += e0.y; v10 += e1.x; v11 += e1.y;
                        }
                        *(float2*)&D[p0] = make_float2(v00, v01);
                        *(float2*)&D[p1] = make_float2(v10, v11);
                    }
                }
            } else {
                int ncb = (s - 9) * 128;
#pragma unroll
                for (int j = 0; j < 4; j++) {
                    int col = ncb + n0 + 8 * j + 2 * t;
                    float bb0 = f1B[col], bb1 = f1B[col + 1];
                    float s0  = f2W[col], s1  = f2W[col + 1];
#pragma unroll
                    for (int i = 0; i < 4; i++) {
                        psum[2*i]   += fmaxf(acc[i][j][0] + bb0, 0.f) * s0
                                     + fmaxf(acc[i][j][1] + bb1, 0.f) * s1;
                        psum[2*i+1] += fmaxf(acc[i][j][2] + bb0, 0.f) * s0
                                     + fmaxf(acc[i][j][3] + bb1, 0.f) * s1;
                    }
                }
            }
        }

        if (q + 1 < NSLOT) cp_wait<0>();
        __syncthreads();
    }

    float (*red)[17] = (float(*)[17])Wc;
    const int qn = (wid & 3) * 4 + t;
#pragma unroll
    for (int i = 0; i < 4; i++) {
        red[m0 + 16 * i + g    ][qn] = psum[2*i];
        red[m0 + 16 * i + g + 8][qn] = psum[2*i+1];
    }
    __syncthreads();
    if (tid < 128) {
        float sum = f2B[0];
#pragma unroll
        for (int k = 0; k < 16; k++) sum += red[tid][k];
        out[row0 + tid] = sum;
    }
}

// ---------------------------------------------------------------------------
extern "C" void kernel_launch(void* const* d_in, const int* in_sizes, int n_in,
                              void* d_out, int out_size)
{
    const float* G     = (const float*)d_in[0];
    const float* xG    = (const float*)d_in[1];
    const float* gmlW  = (const float*)d_in[2];
    const float* gmlB  = (const float*)d_in[3];
    const float* lin0W = (const float*)d_in[4];
    const float* lin0B = (const float*)d_in[5];
    const float* rinW  = (const float*)d_in[6];
    const float* rinB  = (const float*)d_in[7];
    const float* rb1W  = (const float*)d_in[8];
    const float* rb1B  = (const float*)d_in[9];
    const float* rb2W  = (const float*)d_in[10];
    const float* routW = (const float*)d_in[11];
    const float* routB = (const float*)d_in[12];
    const float* f1W   = (const float*)d_in[13];
    const float* f1B   = (const float*)d_in[14];
    const float* f2W   = (const float*)d_in[15];
    const float* f2B   = (const float*)d_in[16];
    float* out = (float*)d_out;

    float *bX;
    cudaGetSymbolAddress((void**)&bX, g_X);

    cudaFuncSetAttribute(gnn_fused,
                         cudaFuncAttributeMaxDynamicSharedMemorySize, DSMEM_GNN);
    cudaFuncSetAttribute(trunk_head_fused,
                         cudaFuncAttributeMaxDynamicSharedMemorySize, DSMEM_TRUNK);

    // All 4 GNN layers in one kernel: one block per batch
    gnn_fused<<<B_, 512, DSMEM_GNN>>>(G, xG, gmlW, gmlB, bX);

    // Fused MLP trunk + head
    trunk_head_fused<<<BM_ / 128, 256, DSMEM_TRUNK>>>(bX,
        lin0W, lin0B, rinW, rinB, rb1W, rb1B, rb2W, routW, routB,
        f1W, f1B, f2W, f2B, out);
}

// round 10
// speedup vs baseline: 1.1485x; 1.1485x over previous
#include <cuda_runtime.h>
#include <cstdint>

#define B_   512
#define M_   256
#define BM_  (B_*M_)      // 131072 rows
#define NGL  4

// Scratch (allocation-free rule: __device__ globals)
__device__ float g_Y[BM_*128];
__device__ float g_X[BM_*128];

// ---------------------------------------------------------------------------
// helpers
// ---------------------------------------------------------------------------
__device__ __forceinline__ uint32_t f2tf(float x) {
    uint32_t r;
    asm("cvt.rna.tf32.f32 %0, %1;" : "=r"(r) : "f"(x));
    return r;
}

__device__ __forceinline__ void mma8(float& c0, float& c1, float& c2, float& c3,
                                     uint32_t a0, uint32_t a1, uint32_t a2, uint32_t a3,
                                     uint32_t b0, uint32_t b1)
{
    asm volatile(
        "mma.sync.aligned.m16n8k8.row.col.f32.tf32.tf32.f32 "
        "{%0,%1,%2,%3}, {%4,%5,%6,%7}, {%8,%9}, {%0,%1,%2,%3};"
        : "+f"(c0), "+f"(c1), "+f"(c2), "+f"(c3)
        : "r"(a0), "r"(a1), "r"(a2), "r"(a3), "r"(b0), "r"(b1));
}

__device__ __forceinline__ uint32_t sptr(const void* p) {
    return (uint32_t)__cvta_generic_to_shared(p);
}
__device__ __forceinline__ void cp16(uint32_t s, const void* g) {
    asm volatile("cp.async.cg.shared.global [%0], [%1], 16;" :: "r"(s), "l"(g));
}
__device__ __forceinline__ void cp_commit() {
    asm volatile("cp.async.commit_group;");
}
template<int N> __device__ __forceinline__ void cp_wait() {
    asm volatile("cp.async.wait_group %0;" :: "n"(N));
}

// Chunk tiles: [128][ASTR] floats. ASTR=36 => conflict-free frag reads.
#define ASTR 36
// bmm B tile: [32][BSTR] floats (k-major). BSTR=136 => bank=(8t+g)%32.
#define BSTR 136

#define TILE_F   (128*ASTR)              // 4608 floats
#define STG_GEMM (TILE_F*2)
#define STG_BMM  (TILE_F + 32*BSTR)      // 8960 floats
#define DSMEM_GEMM  (STG_GEMM*2*4)       // 73728 B (2-stage)
#define DSMEM_BMM3  (STG_BMM*3*4)        // 107520 B (3-stage)

// ---------------------------------------------------------------------------
// warp-tile compute over one 32-k chunk (padded tiles), 64x32 warp tile.
// ---------------------------------------------------------------------------
template<bool BKM>
__device__ __forceinline__ void compute_chunk(const float* __restrict__ A_s,
                                              const float* __restrict__ B_s,
                                              int m0, int n0, int g, int t,
                                              float acc[4][4][4])
{
#pragma unroll
    for (int ks = 0; ks < 4; ks++) {
        const int k0 = ks * 8;
        uint32_t af[4][4];
#pragma unroll
        for (int i = 0; i < 4; i++) {
            int mr = m0 + 16 * i;
            af[i][0] = f2tf(A_s[(mr + g    ) * ASTR + k0 + t]);
            af[i][1] = f2tf(A_s[(mr + g + 8) * ASTR + k0 + t]);
            af[i][2] = f2tf(A_s[(mr + g    ) * ASTR + k0 + t + 4]);
            af[i][3] = f2tf(A_s[(mr + g + 8) * ASTR + k0 + t + 4]);
        }
        uint32_t bf[4][2];
#pragma unroll
        for (int j = 0; j < 4; j++) {
            int nb = n0 + 8 * j + g;
            if (BKM) {
                bf[j][0] = f2tf(B_s[(k0 + t    ) * BSTR + nb]);
                bf[j][1] = f2tf(B_s[(k0 + t + 4) * BSTR + nb]);
            } else {
                bf[j][0] = f2tf(B_s[nb * ASTR + k0 + t]);
                bf[j][1] = f2tf(B_s[nb * ASTR + k0 + t + 4]);
            }
        }
#pragma unroll
        for (int i = 0; i < 4; i++)
#pragma unroll
            for (int j = 0; j < 4; j++)
                mma8(acc[i][j][0], acc[i][j][1], acc[i][j][2], acc[i][j][3],
                     af[i][0], af[i][1], af[i][2], af[i][3],
                     bf[j][0], bf[j][1]);
    }
}

// ---------------------------------------------------------------------------
// gml layer GEMM: Y[r,n] = sum_k X[r,k]*W[n,k] + bias[n];  K=N=128.
// ---------------------------------------------------------------------------
__global__ __launch_bounds__(256, 2)
void gemm128_tc(const float* __restrict__ X, const float* __restrict__ W,
                const float* __restrict__ bias, float* __restrict__ Y)
{
    extern __shared__ float sm[];
    const int tid  = threadIdx.x;
    const int lane = tid & 31, wid = tid >> 5;
    const int g = lane >> 2, t = lane & 3;
    const int m0 = (wid >> 2) * 64;
    const int n0 = (wid & 3) * 32;
    const long row0 = (long)blockIdx.x * 128;

    auto fill = [&](int stage, int kc) {
        float* A_s = sm + stage * STG_GEMM;
        float* B_s = A_s + TILE_F;
#pragma unroll
        for (int it = 0; it < 4; it++) {
            int v = tid + it * 256;
            int rr = v >> 3, cc = (v & 7) * 4;
            cp16(sptr(&A_s[rr * ASTR + cc]), &X[(row0 + rr) * 128 + kc + cc]);
            cp16(sptr(&B_s[rr * ASTR + cc]), &W[rr * 128 + kc + cc]);
        }
    };

    float acc[4][4][4];
#pragma unroll
    for (int i = 0; i < 4; i++)
#pragma unroll
        for (int j = 0; j < 4; j++)
#pragma unroll
            for (int q = 0; q < 4; q++) acc[i][j][q] = 0.f;

    fill(0, 0); cp_commit();
#pragma unroll
    for (int c = 0; c < 4; c++) {
        if (c + 1 < 4) { fill((c + 1) & 1, (c + 1) * 32); cp_commit(); cp_wait<1>(); }
        else           { cp_wait<0>(); }
        __syncthreads();
        const float* A_s = sm + (c & 1) * STG_GEMM;
        compute_chunk<false>(A_s, A_s + TILE_F, m0, n0, g, t, acc);
        __syncthreads();
    }

#pragma unroll
    for (int j = 0; j < 4; j++) {
        int col = n0 + 8 * j + 2 * t;
        float bv0 = bias[col], bv1 = bias[col + 1];
#pragma unroll
        for (int i = 0; i < 4; i++) {
            long r0 = row0 + m0 + 16 * i + g;
            long r1 = r0 + 8;
            *(float2*)&Y[r0 * 128 + col] = make_float2(acc[i][j][0] + bv0,
                                                       acc[i][j][1] + bv1);
            *(float2*)&Y[r1 * 128 + col] = make_float2(acc[i][j][2] + bv0,
                                                       acc[i][j][3] + bv1);
        }
    }
}

// ---------------------------------------------------------------------------
// Xout[b,m,p] = relu( sum_n G0[b,m,n] * Yin[b,n,p] );  K=256, 3-stage ring.
// ---------------------------------------------------------------------------
__global__ __launch_bounds__(256, 2)
void bmm_relu_tc(const float* __restrict__ G, const float* __restrict__ Yin,
                 float* __restrict__ Xout)
{
    extern __shared__ float sm[];
    const int tid  = threadIdx.x;
    const int lane = tid & 31, wid = tid >> 5;
    const int g = lane >> 2, t = lane & 3;
    const int m0 = (wid >> 2) * 64;
    const int n0 = (wid & 3) * 32;
    const int b = blockIdx.y;
    const int row0 = blockIdx.x * 128;
    const float* A  = G   + (long)b * M_ * M_;
    const float* Bm = Yin + (long)b * M_ * 128;

    auto fill = [&](int stage, int kc) {
        float* A_s = sm + stage * STG_BMM;
        float* B_s = A_s + TILE_F;
#pragma unroll
        for (int it = 0; it < 4; it++) {
            int v = tid + it * 256;
            int rr = v >> 3, cc = (v & 7) * 4;
            cp16(sptr(&A_s[rr * ASTR + cc]), &A[(row0 + rr) * 256 + kc + cc]);
            int kk = v >> 5, nn = (v & 31) * 4;
            cp16(sptr(&B_s[kk * BSTR + nn]), &Bm[(kc + kk) * 128 + nn]);
        }
    };

    float acc[4][4][4];
#pragma unroll
    for (int i = 0; i < 4; i++)
#pragma unroll
        for (int j = 0; j < 4; j++)
#pragma unroll
            for (int q = 0; q < 4; q++) acc[i][j][q] = 0.f;

    fill(0, 0); cp_commit();
    fill(1, 32); cp_commit();
    for (int c = 0; c < 8; c++) {
        if (c + 2 < 8) { fill((c + 2) % 3, (c + 2) * 32); cp_commit(); cp_wait<2>(); }
        else if (c + 1 < 8) cp_wait<1>();
        else                cp_wait<0>();
        __syncthreads();
        const float* A_s = sm + (c % 3) * STG_BMM;
        compute_chunk<true>(A_s, A_s + TILE_F, m0, n0, g, t, acc);
        __syncthreads();
    }

    float* O = Xout + (long)b * M_ * 128;
#pragma unroll
    for (int j = 0; j < 4; j++) {
        int col = n0 + 8 * j + 2 * t;
#pragma unroll
        for (int i = 0; i < 4; i++) {
            int r0 = row0 + m0 + 16 * i + g;
            int r1 = r0 + 8;
            *(float2*)&O[r0 * 128 + col] =
                make_float2(fmaxf(acc[i][j][0], 0.f), fmaxf(acc[i][j][1], 0.f));
            *(float2*)&O[r1 * 128 + col] =
                make_float2(fmaxf(acc[i][j][2], 0.f), fmaxf(acc[i][j][3], 0.f));
        }
    }
}

// ===========================================================================
// Mega-fused trunk + head, 64-row blocks for 2 blocks/SM.
// smem: H0,H1 swizzled 64x128 tiles + 2 weight chunk buffers = 100 KB.
// Stages: 0 lin0, 1 rin, {2,4,6} rb1_i (bias+relu), {3,5,7} rb2_i (+res),
//         8 rout, 9..16 head n-chunks. 68 chunk-slots.
// ===========================================================================
#define HT64_F  (64*128)
#define WCHK_TF TILE_F
#define DSMEM_TRUNK ((2*HT64_F + 2*WCHK_TF)*4)   // 102400 B
#define NSTG 17
#define NSLOT (NSTG*4)

__global__ __launch_bounds__(256, 2)
void trunk_head_fused(const float* __restrict__ X,
    const float* __restrict__ lin0W, const float* __restrict__ lin0B,
    const float* __restrict__ rinW,  const float* __restrict__ rinB,
    const float* __restrict__ rb1W,  const float* __restrict__ rb1B,
    const float* __restrict__ rb2W,
    const float* __restrict__ routW, const float* __restrict__ routB,
    const float* __restrict__ f1W,   const float* __restrict__ f1B,
    const float* __restrict__ f2W,   const float* __restrict__ f2B,
    float* __restrict__ out)
{
    extern __shared__ float sm[];
    float* H0 = sm;                        // swizzled [64][128]
    float* H1 = sm + HT64_F;
    float* Wc = sm + 2 * HT64_F;           // 2 x [128][ASTR]

    const int tid  = threadIdx.x;
    const int lane = tid & 31, wid = tid >> 5;
    const int g = lane >> 2, t = lane & 3;
    const int m0 = (wid >> 2) * 32;        // 0 or 32 (warp tile 32x32)
    const int n0 = (wid & 3) * 32;
    const long row0 = (long)blockIdx.x * 64;

    const float* wp[NSTG];
    wp[0] = lin0W;  wp[1] = rinW;
    wp[2] = rb1W;            wp[3] = rb2W;
    wp[4] = rb1W + 16384;    wp[5] = rb2W + 16384;
    wp[6] = rb1W + 32768;    wp[7] = rb2W + 32768;
    wp[8] = routW;
#pragma unroll
    for (int i = 0; i < 8; i++) wp[9 + i] = f1W + (long)i * 16384;
    const float* bp[9] = { lin0B, rinB, rb1B, nullptr, rb1B + 128, nullptr,
                           rb1B + 256, nullptr, routB };

    auto fillWchunk = [&](int buf, int slot) {
        const float* Wp = wp[slot >> 2];
        int kc = (slot & 3) * 32;
        float* W_s = Wc + buf * WCHK_TF;
#pragma unroll
        for (int it = 0; it < 4; it++) {
            int v = tid + it * 256;
            int rr = v >> 3, cc = (v & 7) * 4;
            cp16(sptr(&W_s[rr * ASTR + cc]), &Wp[rr * 128 + kc + cc]);
        }
    };

    // prologue: X rows -> H0 (swizzled), weight chunk 0 -> buf 0
#pragma unroll
    for (int it = 0; it < 8; it++) {
        int v = tid + it * 256;
        int rr = v >> 5, cc = (v & 31) * 4;
        cp16(sptr(&H0[rr * 128 + (cc ^ ((rr & 7) << 2))]),
             &X[(row0 + rr) * 128 + cc]);
    }
    fillWchunk(0, 0);
    cp_commit(); cp_wait<0>(); __syncthreads();

    float psum[4];
#pragma unroll
    for (int q = 0; q < 4; q++) psum[q] = 0.f;

    float acc[2][4][4];

    for (int q = 0; q < NSLOT; q++) {
        const int s = q >> 2, c = q & 3;

        if (q + 1 < NSLOT) { fillWchunk((q + 1) & 1, q + 1); cp_commit(); }

        if (c == 0) {
#pragma unroll
            for (int i = 0; i < 2; i++)
#pragma unroll
                for (int j = 0; j < 4; j++)
#pragma unroll
                    for (int z = 0; z < 4; z++) acc[i][j][z] = 0.f;
        }

        const float* H_s = ((s & 1) || s >= 9) ? H1 : H0;
        const float* W_s = Wc + (q & 1) * WCHK_TF;
        const int kc = c * 32;
        const int sw = g << 2;
#pragma unroll
        for (int ks = 0; ks < 4; ks++) {
            const int k0 = ks * 8;
            uint32_t af[2][4];
#pragma unroll
            for (int i = 0; i < 2; i++) {
                int r0 = m0 + 16 * i + g;    // (r&7)==g
                int r1 = r0 + 8;
                af[i][0] = f2tf(H_s[r0 * 128 + ((kc + k0 + t    ) ^ sw)]);
                af[i][1] = f2tf(H_s[r1 * 128 + ((kc + k0 + t    ) ^ sw)]);
                af[i][2] = f2tf(H_s[r0 * 128 + ((kc + k0 + t + 4) ^ sw)]);
                af[i][3] = f2tf(H_s[r1 * 128 + ((kc + k0 + t + 4) ^ sw)]);
            }
            uint32_t bf[4][2];
#pragma unroll
            for (int j = 0; j < 4; j++) {
                int nb = n0 + 8 * j + g;
                bf[j][0] = f2tf(W_s[nb * ASTR + k0 + t]);
                bf[j][1] = f2tf(W_s[nb * ASTR + k0 + t + 4]);
            }
#pragma unroll
            for (int i = 0; i < 2; i++)
#pragma unroll
                for (int j = 0; j < 4; j++)
                    mma8(acc[i][j][0], acc[i][j][1], acc[i][j][2], acc[i][j][3],
                         af[i][0], af[i][1], af[i][2], af[i][3],
                         bf[j][0], bf[j][1]);
        }

        if (c == 3) {
            if (s < 9) {
                float* D = (s & 1) ? H0 : H1;
                const bool relu = (s == 2 || s == 4 || s == 6);
                const bool res  = (s == 3 || s == 5 || s == 7);
                const float* bias = bp[s];
#pragma unroll
                for (int j = 0; j < 4; j++) {
                    int col = n0 + 8 * j + 2 * t;
                    float bv0 = bias ? bias[col]     : 0.f;
                    float bv1 = bias ? bias[col + 1] : 0.f;
#pragma unroll
                    for (int i = 0; i < 2; i++) {
                        int r0 = m0 + 16 * i + g;   // (r&7)==g
                        int r1 = r0 + 8;
                        int p0 = r0 * 128 + (col ^ sw);
                        int p1 = r1 * 128 + (col ^ sw);
                        float v00 = acc[i][j][0] + bv0, v01 = acc[i][j][1] + bv1;
                        float v10 = acc[i][j][2] + bv0, v11 = acc[i][j][3] + bv1;
                        if (relu) { v00 = fmaxf(v00, 0.f); v01 = fmaxf(v01, 0.f);
                                    v10 = fmaxf(v10, 0.f); v11 = fmaxf(v11, 0.f); }
                        if (res) {
                            float2 e0 = *(const float2*)&D[p0];
                            float2 e1 = *(const float2*)&D[p1];
                            v00 += e0.x; v01 += e0.y; v10 += e1.x; v11 += e1.y;
                        }
                        *(float2*)&D[p0] = make_float2(v00, v01);
                        *(float2*)&D[p1] = make_float2(v10, v11);
                    }
                }
            } else {
                int ncb = (s - 9) * 128;
#pragma unroll
                for (int j = 0; j < 4; j++) {
                    int col = ncb + n0 + 8 * j + 2 * t;
                    float bb0 = f1B[col], bb1 = f1B[col + 1];
                    float s0  = f2W[col], s1  = f2W[col + 1];
#pragma unroll
                    for (int i = 0; i < 2; i++) {
                        psum[2*i]   += fmaxf(acc[i][j][0] + bb0, 0.f) * s0
                                     + fmaxf(acc[i][j][1] + bb1, 0.f) * s1;
                        psum[2*i+1] += fmaxf(acc[i][j][2] + bb0, 0.f) * s0
                                     + fmaxf(acc[i][j][3] + bb1, 0.f) * s1;
                    }
                }
            }
        }

        if (q + 1 < NSLOT) cp_wait<0>();
        __syncthreads();
    }

    // reduce 16 partials per row; overlay scratch on weight buffers
    float (*red)[17] = (float(*)[17])Wc;
    const int qn = (wid & 3) * 4 + t;
#pragma unroll
    for (int i = 0; i < 2; i++) {
        red[m0 + 16 * i + g    ][qn] = psum[2*i];
        red[m0 + 16 * i + g + 8][qn] = psum[2*i+1];
    }
    __syncthreads();
    if (tid < 64) {
        float sum = f2B[0];
#pragma unroll
        for (int k = 0; k < 16; k++) sum += red[tid][k];
        out[row0 + tid] = sum;
    }
}

// ---------------------------------------------------------------------------
extern "C" void kernel_launch(void* const* d_in, const int* in_sizes, int n_in,
                              void* d_out, int out_size)
{
    const float* G     = (const float*)d_in[0];
    const float* xG    = (const float*)d_in[1];
    const float* gmlW  = (const float*)d_in[2];
    const float* gmlB  = (const float*)d_in[3];
    const float* lin0W = (const float*)d_in[4];
    const float* lin0B = (const float*)d_in[5];
    const float* rinW  = (const float*)d_in[6];
    const float* rinB  = (const float*)d_in[7];
    const float* rb1W  = (const float*)d_in[8];
    const float* rb1B  = (const float*)d_in[9];
    const float* rb2W  = (const float*)d_in[10];
    const float* routW = (const float*)d_in[11];
    const float* routB = (const float*)d_in[12];
    const float* f1W   = (const float*)d_in[13];
    const float* f1B   = (const float*)d_in[14];
    const float* f2W   = (const float*)d_in[15];
    const float* f2B   = (const float*)d_in[16];
    float* out = (float*)d_out;

    float *bY, *bX;
    cudaGetSymbolAddress((void**)&bY, g_Y);
    cudaGetSymbolAddress((void**)&bX, g_X);

    cudaFuncSetAttribute(gemm128_tc,
                         cudaFuncAttributeMaxDynamicSharedMemorySize, DSMEM_GEMM);
    cudaFuncSetAttribute(bmm_relu_tc,
                         cudaFuncAttributeMaxDynamicSharedMemorySize, DSMEM_BMM3);
    cudaFuncSetAttribute(trunk_head_fused,
                         cudaFuncAttributeMaxDynamicSharedMemorySize, DSMEM_TRUNK);

    const int GB = BM_ / 128;   // 1024 blocks
    dim3 blk(256);

    // GNN message-passing layers (split kernels — R8-proven)
    const float* xcur = xG;
    for (int l = 0; l < NGL; l++) {
        gemm128_tc<<<GB, blk, DSMEM_GEMM>>>(xcur, gmlW + (long)l * 16384,
                                            gmlB + l * 128, bY);
        bmm_relu_tc<<<dim3(2, B_), blk, DSMEM_BMM3>>>(G, bY, bX);
        xcur = bX;
    }

    // Fused MLP trunk + head (64-row blocks, 2 blocks/SM)
    trunk_head_fused<<<BM_ / 64, blk, DSMEM_TRUNK>>>(bX,
        lin0W, lin0B, rinW, rinB, rb1W, rb1B, rb2W, routW, routB,
        f1W, f1B, f2W, f2B, out);
}